// round 5
// baseline (speedup 1.0000x reference)
#include <cuda_runtime.h>

#define NB 2048
#define NN 64
#define DM 512
#define NH 4
#define DK 128
#define TB 16

typedef unsigned long long ull;

__device__ float g_Wqf[DM * NH];
__device__ float g_Wkf[DM * NH];
__device__ float g_ctx[NB * NH * DM];   // [b][h][i]

// ---- f32x2 packed helpers (sm_100+) ----------------------------------------
__device__ __forceinline__ ull pk(float a, float b) {
    ull r; asm("mov.b64 %0,{%1,%2};" : "=l"(r) : "f"(a), "f"(b)); return r;
}
__device__ __forceinline__ void fma2(ull &d, ull a, ull b) {
    asm("fma.rn.f32x2 %0,%1,%2,%0;" : "+l"(d) : "l"(a), "l"(b));
}
__device__ __forceinline__ ull add2(ull a, ull b) {
    ull r; asm("add.rn.f32x2 %0,%1,%2;" : "=l"(r) : "l"(a), "l"(b)); return r;
}
__device__ __forceinline__ ull mul2(ull a, ull b) {
    ull r; asm("mul.rn.f32x2 %0,%1,%2;" : "=l"(r) : "l"(a), "l"(b)); return r;
}
__device__ __forceinline__ float2 up(ull a) {
    float2 f; asm("mov.b64 {%0,%1},%2;" : "=f"(f.x), "=f"(f.y) : "l"(a)); return f;
}
__device__ __forceinline__ void barg(int id) {
    asm volatile("bar.sync %0, 128;" :: "r"(id) : "memory");
}

// ---------------------------------------------------------------------------
// K0: fold Wq/Wk with w_map halves. grid 512, block 128.
// ---------------------------------------------------------------------------
__global__ void __launch_bounds__(128) fold_kernel(
    const float* __restrict__ Wq, const float* __restrict__ Wk,
    const float* __restrict__ w_map)
{
    __shared__ float4 s_m[64];
    int i = blockIdx.x;
    int t = threadIdx.x;
    int lane = t & 31, h = t >> 5;
    if (t < 64) s_m[t] = ((const float4*)w_map)[t];
    __syncthreads();
    float4 vq = ((const float4*)(Wq + i * DM + h * DK))[lane];
    float4 vk = ((const float4*)(Wk + i * DM + h * DK))[lane];
    float4 mq = s_m[lane], mk = s_m[32 + lane];
    float sq = vq.x * mq.x + vq.y * mq.y + vq.z * mq.z + vq.w * mq.w;
    float sk = vk.x * mk.x + vk.y * mk.y + vk.z * mk.z + vk.w * mk.w;
#pragma unroll
    for (int o = 16; o > 0; o >>= 1) {
        sq += __shfl_xor_sync(0xffffffffu, sq, o);
        sk += __shfl_xor_sync(0xffffffffu, sk, o);
    }
    if (lane == 0) {
        g_Wqf[i * NH + h] = sq;
        g_Wkf[i * NH + h] = sk;
    }
}

// ---------------------------------------------------------------------------
// K1: fused scores + online softmax + ctx, ONE k_in read.
// block 512 = 4 batch-groups x 4 warps (one k_in segment per warp).
// grid 512 (4 batches per CTA).
// ---------------------------------------------------------------------------
__global__ void __launch_bounds__(512, 1) fused_attn_kernel(
    const float* __restrict__ src,  const float* __restrict__ srct,
    const float* __restrict__ srcp,
    const float* __restrict__ seq,  const float* __restrict__ seqe,
    const float* __restrict__ seqt, const float* __restrict__ seqp,
    const int*   __restrict__ mask, float* __restrict__ out_attn)
{
    __shared__ float4 s_qsp[4][4];      // [g][s] per-warp q_score partials (4 heads)
    __shared__ float4 s_kp[4][4][2];    // [g][s][k&1] per-warp k_score partials
    __shared__ int    s_msk[4][NN];
    __shared__ float  s_raw[4][NN * 4]; // raw masked scores [k][h]
    __shared__ float  s_mst[4][8];      // m[4], inv_l[4]

    int t = threadIdx.x;
    int lane = t & 31;
    int s = (t >> 5) & 3;               // segment (0:seq/src 1:seqe/0 2:seqt 3:seqp)
    int g = t >> 7;                     // batch group in CTA
    int b = blockIdx.x * 4 + g;

    // per-lane folded-Wk weights for its 4 i's (i = s*128 + lane*4 + j)
    ull wk01[4], wk23[4];
    const float4* gwk = (const float4*)g_Wkf;
#pragma unroll
    for (int j = 0; j < 4; j++) {
        float4 w = gwk[s * DK + lane * 4 + j];
        wk01[j] = pk(w.x, w.y);
        wk23[j] = pk(w.z, w.w);
    }

    // q_score partial for this warp's segment (seg 1 of q_in is zero)
    ull qA = 0, qB = 0;
    if (s != 1) {
        const float* qarr = (s == 0) ? src : (s == 2) ? srct : srcp;
        float4 v = ((const float4*)(qarr + (size_t)b * DK))[lane];
        const float4* gwq = (const float4*)g_Wqf;
#pragma unroll
        for (int j = 0; j < 4; j++) {
            float4 w = gwq[s * DK + lane * 4 + j];
            float vj = (j == 0) ? v.x : (j == 1) ? v.y : (j == 2) ? v.z : v.w;
            ull d = pk(vj, vj);
            fma2(qA, d, pk(w.x, w.y));
            fma2(qB, d, pk(w.z, w.w));
        }
#pragma unroll
        for (int o = 16; o > 0; o >>= 1) {
            qA = add2(qA, __shfl_xor_sync(0xffffffffu, qA, o));
            qB = add2(qB, __shfl_xor_sync(0xffffffffu, qB, o));
        }
    } else {
        // warp 1 preloads the mask instead
        s_msk[g][lane]      = mask[(size_t)b * NN + lane];
        s_msk[g][32 + lane] = mask[(size_t)b * NN + 32 + lane];
    }
    if (lane == 0) {
        float2 a = up(qA), c = up(qB);
        s_qsp[g][s] = make_float4(a.x, a.y, c.x, c.y);
    }
    barg(g);
    float qs0, qs1, qs2, qs3;
    {
        float4 p0 = s_qsp[g][0], p1 = s_qsp[g][1];
        float4 p2 = s_qsp[g][2], p3 = s_qsp[g][3];
        qs0 = p0.x + p1.x + p2.x + p3.x;
        qs1 = p0.y + p1.y + p2.y + p3.y;
        qs2 = p0.z + p1.z + p2.z + p3.z;
        qs3 = p0.w + p1.w + p2.w + p3.w;
    }

    // stream pointer: this warp's float4 column of its segment
    const float* karr = (s == 0) ? seq : (s == 1) ? seqe : (s == 2) ? seqt : seqp;
    const float4* kp_ = (const float4*)(karr + (size_t)b * NN * DK) + lane;

    float m0 = -1e10f, m1 = -1e10f, m2 = -1e10f, m3 = -1e10f;
    float l0 = 0.f, l1 = 0.f, l2 = 0.f, l3 = 0.f;
    ull c00 = 0, c01 = 0, c10 = 0, c11 = 0, c20 = 0, c21 = 0, c30 = 0, c31 = 0;

    float4 vc = kp_[0];
#pragma unroll 2
    for (int k = 0; k < NN; k++) {
        float4 vn = kp_[((k < NN - 1) ? k + 1 : NN - 1) * 32];

        // segment-partial scores (4 heads)
        ull sA = 0, sB = 0;
        {
            ull d0 = pk(vc.x, vc.x), d1 = pk(vc.y, vc.y);
            ull d2 = pk(vc.z, vc.z), d3 = pk(vc.w, vc.w);
            fma2(sA, d0, wk01[0]); fma2(sB, d0, wk23[0]);
            fma2(sA, d1, wk01[1]); fma2(sB, d1, wk23[1]);
            fma2(sA, d2, wk01[2]); fma2(sB, d2, wk23[2]);
            fma2(sA, d3, wk01[3]); fma2(sB, d3, wk23[3]);
        }
#pragma unroll
        for (int o = 16; o > 0; o >>= 1) {
            sA = add2(sA, __shfl_xor_sync(0xffffffffu, sA, o));
            sB = add2(sB, __shfl_xor_sync(0xffffffffu, sB, o));
        }
        if (lane == 0) {
            float2 a = up(sA), c = up(sB);
            s_kp[g][s][k & 1] = make_float4(a.x, a.y, c.x, c.y);
        }
        barg(g);

        float4 f0 = s_kp[g][0][k & 1], f1 = s_kp[g][1][k & 1];
        float4 f2 = s_kp[g][2][k & 1], f3 = s_kp[g][3][k & 1];
        float v0 = qs0 + f0.x + f1.x + f2.x + f3.x;
        float v1 = qs1 + f0.y + f1.y + f2.y + f3.y;
        float v2 = qs2 + f0.z + f1.z + f2.z + f3.z;
        float v3 = qs3 + f0.w + f1.w + f2.w + f3.w;
        if (s_msk[g][k]) { v0 = -1e10f; v1 = -1e10f; v2 = -1e10f; v3 = -1e10f; }

        float n0 = fmaxf(m0, v0), n1 = fmaxf(m1, v1);
        float n2 = fmaxf(m2, v2), n3 = fmaxf(m3, v3);
        if (n0 != m0 || n1 != m1 || n2 != m2 || n3 != m3) {
            float r0 = __expf(m0 - n0), r1 = __expf(m1 - n1);
            float r2 = __expf(m2 - n2), r3 = __expf(m3 - n3);
            l0 *= r0; l1 *= r1; l2 *= r2; l3 *= r3;
            ull R0 = pk(r0, r0), R1 = pk(r1, r1), R2 = pk(r2, r2), R3 = pk(r3, r3);
            c00 = mul2(c00, R0); c01 = mul2(c01, R0);
            c10 = mul2(c10, R1); c11 = mul2(c11, R1);
            c20 = mul2(c20, R2); c21 = mul2(c21, R2);
            c30 = mul2(c30, R3); c31 = mul2(c31, R3);
            m0 = n0; m1 = n1; m2 = n2; m3 = n3;
        }
        float e0 = __expf(v0 - m0), e1 = __expf(v1 - m1);
        float e2 = __expf(v2 - m2), e3 = __expf(v3 - m3);
        l0 += e0; l1 += e1; l2 += e2; l3 += e3;

        ull vp0 = pk(vc.x, vc.y), vp1 = pk(vc.z, vc.w);
        ull E0 = pk(e0, e0), E1 = pk(e1, e1), E2 = pk(e2, e2), E3 = pk(e3, e3);
        fma2(c00, E0, vp0); fma2(c01, E0, vp1);
        fma2(c10, E1, vp0); fma2(c11, E1, vp1);
        fma2(c20, E2, vp0); fma2(c21, E2, vp1);
        fma2(c30, E3, vp0); fma2(c31, E3, vp1);

        if (s == 0 && lane == 0)
            ((float4*)s_raw[g])[k] = make_float4(v0, v1, v2, v3);
        vc = vn;
    }

    // finalize: normalize ctx, write to global
    float i0 = 1.f / l0, i1 = 1.f / l1, i2 = 1.f / l2, i3 = 1.f / l3;
    ull I0 = pk(i0, i0), I1 = pk(i1, i1), I2 = pk(i2, i2), I3 = pk(i3, i3);
    c00 = mul2(c00, I0); c01 = mul2(c01, I0);
    c10 = mul2(c10, I1); c11 = mul2(c11, I1);
    c20 = mul2(c20, I2); c21 = mul2(c21, I2);
    c30 = mul2(c30, I3); c31 = mul2(c31, I3);

    float4* gc = (float4*)g_ctx + (size_t)b * DM;   // 512 float4 per batch
    {
        float2 a, c;
        a = up(c00); c = up(c01); gc[0 * DK + s * 32 + lane] = make_float4(a.x, a.y, c.x, c.y);
        a = up(c10); c = up(c11); gc[1 * DK + s * 32 + lane] = make_float4(a.x, a.y, c.x, c.y);
        a = up(c20); c = up(c21); gc[2 * DK + s * 32 + lane] = make_float4(a.x, a.y, c.x, c.y);
        a = up(c30); c = up(c31); gc[3 * DK + s * 32 + lane] = make_float4(a.x, a.y, c.x, c.y);
    }
    if (s == 0 && lane == 0) {
        s_mst[g][0] = m0; s_mst[g][1] = m1; s_mst[g][2] = m2; s_mst[g][3] = m3;
        s_mst[g][4] = i0; s_mst[g][5] = i1; s_mst[g][6] = i2; s_mst[g][7] = i3;
    }
    barg(g);

    // attn output: 256 values per batch, 128 threads -> 2 each
    int t2 = s * 32 + lane;
#pragma unroll
    for (int jj = 0; jj < 2; jj++) {
        int j = t2 * 2 + jj;
        int kk = j >> 2, h = j & 3;
        float raw = s_raw[g][j];
        float a = __expf(raw - s_mst[g][h]) * s_mst[g][4 + h];
        out_attn[(size_t)b * (NH * NN) + h * NN + kk] = a;
    }
}

// ---------------------------------------------------------------------------
// K2: GEMM chain, TB=16 batches/CTA, 128 CTAs, block 512, 1 CTA/SM.
// ---------------------------------------------------------------------------
#define SM_CTX  0        // [16][2048] f (32768) ; aliases: ln [16][512], h1
#define SM_OUT  32768    // [16][512]  (8192)    ; alias: part [3][16][128]
#define SM_SRC  40960    // [16][128]  (2048)
#define SM_TOTF 43008
#define SM_H1   8192     // alias in ctx region (after ln's 8192 floats)

__global__ void __launch_bounds__(512) tail_kernel(
    const float* __restrict__ src,  const float* __restrict__ srct,
    const float* __restrict__ srcp,
    const float* __restrict__ Wv,   const float* __restrict__ fcw,
    const float* __restrict__ fcb,  const float* __restrict__ lng,
    const float* __restrict__ lnb,  const float* __restrict__ fc1w,
    const float* __restrict__ fc1b, const float* __restrict__ fc2w,
    const float* __restrict__ fc2b, float* __restrict__ zout)
{
    extern __shared__ float sm[];
    ulonglong2* ctxU = (ulonglong2*)sm;
    float*      out_s = sm + SM_OUT;
    ulonglong2* outU  = (ulonglong2*)out_s;
    float*      src_s = sm + SM_SRC;
    ulonglong2* srcU  = (ulonglong2*)src_s;
    float*      ln_s  = sm;
    ulonglong2* lnU   = (ulonglong2*)sm;
    float*      h1_s  = sm + SM_H1;
    ulonglong2* h1U   = (ulonglong2*)h1_s;
    float*      part  = out_s;            // alias, used in phases 5/6

    int t = threadIdx.x;
    int b0 = blockIdx.x * TB;

    // stage ctx + src
    {
        const float4* gc = (const float4*)g_ctx + (size_t)b0 * DM;
        float4* c4 = (float4*)sm;
        for (int idx = t; idx < TB * NH * DM / 4; idx += 512) c4[idx] = gc[idx];
        const float4* gs = (const float4*)(src + (size_t)b0 * DK);
        float4* s4 = (float4*)src_s;
        for (int idx = t; idx < TB * DK / 4; idx += 512) s4[idx] = gs[idx];
    }
    __syncthreads();

    int h = t >> 7, d = t & 127;

    // Phase 2: out[r][h*128+d] = sum_i ctx[r][h][i] * Wv[i][h*128+d]
    {
        ull acc[TB];
#pragma unroll
        for (int r = 0; r < TB; r++) acc[r] = 0;
        const float* wcol = Wv + h * DK + d;
#pragma unroll 2
        for (int i4 = 0; i4 < 128; i4++) {
            int i = i4 * 4;
            float w0 = wcol[(i + 0) * DM], w1 = wcol[(i + 1) * DM];
            float w2 = wcol[(i + 2) * DM], w3 = wcol[(i + 3) * DM];
            ull wA = pk(w0, w1), wB = pk(w2, w3);
#pragma unroll
            for (int r = 0; r < TB; r++) {
                ulonglong2 c = ctxU[r * 512 + h * 128 + i4];   // broadcast
                fma2(acc[r], c.x, wA);
                fma2(acc[r], c.y, wB);
            }
        }
#pragma unroll
        for (int r = 0; r < TB; r++) {
            float2 f = up(acc[r]);
            out_s[r * DM + h * DK + d] = f.x + f.y;
        }
    }
    __syncthreads();

    // Phase 3: fc + leaky -> ln_s ; thread owns col t
    {
        ull acc[TB];
#pragma unroll
        for (int r = 0; r < TB; r++) acc[r] = 0;
        const float* wcol = fcw + t;
#pragma unroll 2
        for (int i4 = 0; i4 < 128; i4++) {
            int i = i4 * 4;
            float w0 = wcol[(i + 0) * DM], w1 = wcol[(i + 1) * DM];
            float w2 = wcol[(i + 2) * DM], w3 = wcol[(i + 3) * DM];
            ull wA = pk(w0, w1), wB = pk(w2, w3);
#pragma unroll
            for (int r = 0; r < TB; r++) {
                ulonglong2 x = outU[r * 128 + i4];             // broadcast
                fma2(acc[r], x.x, wA);
                fma2(acc[r], x.y, wB);
            }
        }
        float bb = fcb[t];
#pragma unroll
        for (int r = 0; r < TB; r++) {
            float2 f = up(acc[r]);
            float v = f.x + f.y + bb;
            v = (v > 0.f) ? v : 0.2f * v;
            ln_s[r * DM + t] = v;
        }
    }
    __syncthreads();

    // Phase 4: residual (+q_in) + layernorm, warp w -> row w
    {
        int w = t >> 5, l = t & 31;
        int gb = b0 + w;
        float y[16];
        float sum = 0.f, sumsq = 0.f;
#pragma unroll
        for (int e = 0; e < 16; e++) {
            int j = l + e * 32;
            float q;
            if (j < 128)       q = src_s[w * DK + j];
            else if (j < 256)  q = 0.f;
            else if (j < 384)  q = srct[(size_t)gb * DK + (j - 256)];
            else               q = srcp[(size_t)gb * DK + (j - 384)];
            float v = ln_s[w * DM + j] + q;
            y[e] = v; sum += v; sumsq += v * v;
        }
#pragma unroll
        for (int o = 16; o > 0; o >>= 1) {
            sum   += __shfl_xor_sync(0xffffffffu, sum, o);
            sumsq += __shfl_xor_sync(0xffffffffu, sumsq, o);
        }
        float mu  = sum * (1.f / 512.f);
        float var = sumsq * (1.f / 512.f) - mu * mu;
        float inv = rsqrtf(var + 1e-5f);
#pragma unroll
        for (int e = 0; e < 16; e++) {
            int j = l + e * 32;
            ln_s[w * DM + j] = (y[e] - mu) * inv * lng[j] + lnb[j];
        }
    }
    __syncthreads();

    int q = h;   // K-quarter 0..3

    // Phase 5: fc1 (K=640, split 4 ways) + relu -> h1_s
    {
        ull acc[TB];
#pragma unroll
        for (int r = 0; r < TB; r++) acc[r] = 0;
        const float* wcol = fc1w + d;
        int i40 = q * 32;
#pragma unroll 2
        for (int i4 = i40; i4 < i40 + 32; i4++) {
            int j = i4 * 4;
            float w0 = wcol[(j + 0) * DK], w1 = wcol[(j + 1) * DK];
            float w2 = wcol[(j + 2) * DK], w3 = wcol[(j + 3) * DK];
            ull wA = pk(w0, w1), wB = pk(w2, w3);
#pragma unroll
            for (int r = 0; r < TB; r++) {
                ulonglong2 x = lnU[r * 128 + i4];              // broadcast
                fma2(acc[r], x.x, wA); fma2(acc[r], x.y, wB);
            }
        }
        int j40 = q * 8;
#pragma unroll 2
        for (int j4 = j40; j4 < j40 + 8; j4++) {
            int j = j4 * 4;
            float w0 = wcol[(DM + j + 0) * DK], w1 = wcol[(DM + j + 1) * DK];
            float w2 = wcol[(DM + j + 2) * DK], w3 = wcol[(DM + j + 3) * DK];
            ull wA = pk(w0, w1), wB = pk(w2, w3);
#pragma unroll
            for (int r = 0; r < TB; r++) {
                ulonglong2 x = srcU[r * 32 + j4];              // broadcast
                fma2(acc[r], x.x, wA); fma2(acc[r], x.y, wB);
            }
        }
        if (q > 0) {
#pragma unroll
            for (int r = 0; r < TB; r++) {
                float2 f = up(acc[r]);
                part[(q - 1) * 2048 + r * 128 + d] = f.x + f.y;
            }
        }
        __syncthreads();
        if (q == 0) {
            float bb = fc1b[d];
#pragma unroll
            for (int r = 0; r < TB; r++) {
                float2 f = up(acc[r]);
                float v = f.x + f.y + part[0 * 2048 + r * 128 + d]
                        + part[1 * 2048 + r * 128 + d]
                        + part[2 * 2048 + r * 128 + d] + bb;
                h1_s[r * DK + d] = fmaxf(v, 0.f);
            }
        }
        __syncthreads();
    }

    // Phase 6: fc2 (K=128, split 4 ways) -> z
    {
        ull acc[TB];
#pragma unroll
        for (int r = 0; r < TB; r++) acc[r] = 0;
        const float* wcol = fc2w + d;
        int j40 = q * 8;
#pragma unroll 2
        for (int j4 = j40; j4 < j40 + 8; j4++) {
            int j = j4 * 4;
            float w0 = wcol[(j + 0) * DK], w1 = wcol[(j + 1) * DK];
            float w2 = wcol[(j + 2) * DK], w3 = wcol[(j + 3) * DK];
            ull wA = pk(w0, w1), wB = pk(w2, w3);
#pragma unroll
            for (int r = 0; r < TB; r++) {
                ulonglong2 x = h1U[r * 32 + j4];               // broadcast
                fma2(acc[r], x.x, wA); fma2(acc[r], x.y, wB);
            }
        }
        if (q > 0) {
#pragma unroll
            for (int r = 0; r < TB; r++) {
                float2 f = up(acc[r]);
                part[(q - 1) * 2048 + r * 128 + d] = f.x + f.y;
            }
        }
        __syncthreads();
        if (q == 0) {
            float bb = fc2b[d];
#pragma unroll
            for (int r = 0; r < TB; r++) {
                float2 f = up(acc[r]);
                zout[(size_t)(b0 + r) * DK + d] = f.x + f.y
                    + part[0 * 2048 + r * 128 + d]
                    + part[1 * 2048 + r * 128 + d]
                    + part[2 * 2048 + r * 128 + d] + bb;
            }
        }
    }
}

// ---------------------------------------------------------------------------
extern "C" void kernel_launch(void* const* d_in, const int* in_sizes, int n_in,
                              void* d_out, int out_size) {
    (void)in_sizes; (void)n_in; (void)out_size;
    const float* src   = (const float*)d_in[0];
    const float* src_t = (const float*)d_in[1];
    const float* src_p = (const float*)d_in[2];
    const float* seq   = (const float*)d_in[3];
    const float* seq_t = (const float*)d_in[4];
    const float* seq_e = (const float*)d_in[5];
    const float* seq_p = (const float*)d_in[6];
    const int*   mask  = (const int*)d_in[7];
    const float* Wq    = (const float*)d_in[8];
    const float* Wk    = (const float*)d_in[9];
    const float* Wv    = (const float*)d_in[10];
    const float* w_map = (const float*)d_in[11];
    const float* fc_w  = (const float*)d_in[12];
    const float* fc_b  = (const float*)d_in[13];
    const float* ln_g  = (const float*)d_in[14];
    const float* ln_b  = (const float*)d_in[15];
    const float* fc1_w = (const float*)d_in[16];
    const float* fc1_b = (const float*)d_in[17];
    const float* fc2_w = (const float*)d_in[18];
    const float* fc2_b = (const float*)d_in[19];

    float* out      = (float*)d_out;
    float* z_out    = out;                 // [2048,1,128]
    float* attn_out = out + NB * DK;       // [2048,4,1,64]

    fold_kernel<<<DM, 128>>>(Wq, Wk, w_map);
    fused_attn_kernel<<<NB / 4, 512>>>(src, src_t, src_p,
                                       seq, seq_e, seq_t, seq_p,
                                       mask, attn_out);

    const int smem2 = SM_TOTF * (int)sizeof(float);
    cudaFuncSetAttribute(tail_kernel, cudaFuncAttributeMaxDynamicSharedMemorySize, smem2);
    tail_kernel<<<NB / TB, 512, smem2>>>(src, src_t, src_p,
                                         Wv, fc_w, fc_b, ln_g, ln_b,
                                         fc1_w, fc1_b, fc2_w, fc2_b, z_out);
}

// round 9
// speedup vs baseline: 1.4159x; 1.4159x over previous
#include <cuda_runtime.h>

#define NB 2048
#define NN 64
#define DM 512
#define NH 4
#define DK 128
#define TB 16

typedef unsigned long long ull;

__device__ float g_Wqf[DM * NH];
__device__ float g_Wkf[DM * NH];
__device__ float g_attnT[NB * NN * NH];   // [b][k][h]

// ---- f32x2 packed-FMA helpers (sm_100+) ------------------------------------
__device__ __forceinline__ ull pk(float a, float b) {
    ull r; asm("mov.b64 %0,{%1,%2};" : "=l"(r) : "f"(a), "f"(b)); return r;
}
__device__ __forceinline__ void fma2(ull &d, ull a, ull b) {
    asm("fma.rn.f32x2 %0,%1,%2,%0;" : "+l"(d) : "l"(a), "l"(b));
}
__device__ __forceinline__ float2 up(ull a) {
    float2 f; asm("mov.b64 {%0,%1},%2;" : "=f"(f.x), "=f"(f.y) : "l"(a)); return f;
}

// ---------------------------------------------------------------------------
// K0: fold Wq/Wk with w_map halves. grid 512, block 128 (warp = head).
// ---------------------------------------------------------------------------
__global__ void __launch_bounds__(128) fold_kernel(
    const float* __restrict__ Wq, const float* __restrict__ Wk,
    const float* __restrict__ w_map)
{
    __shared__ float4 s_m[64];
    int i = blockIdx.x;
    int t = threadIdx.x;
    int lane = t & 31, h = t >> 5;
    if (t < 64) s_m[t] = ((const float4*)w_map)[t];
    __syncthreads();
    float4 vq = ((const float4*)(Wq + i * DM + h * DK))[lane];
    float4 vk = ((const float4*)(Wk + i * DM + h * DK))[lane];
    float4 mq = s_m[lane], mk = s_m[32 + lane];
    float sq = vq.x * mq.x + vq.y * mq.y + vq.z * mq.z + vq.w * mq.w;
    float sk = vk.x * mk.x + vk.y * mk.y + vk.z * mk.z + vk.w * mk.w;
#pragma unroll
    for (int o = 16; o > 0; o >>= 1) {
        sq += __shfl_xor_sync(0xffffffffu, sq, o);
        sk += __shfl_xor_sync(0xffffffffu, sk, o);
    }
    if (lane == 0) {
        g_Wqf[i * NH + h] = sq;
        g_Wkf[i * NH + h] = sk;
    }
}

// ---------------------------------------------------------------------------
// K1: scores + masked softmax. grid 2048, block 256. (R3 version, proven)
// ---------------------------------------------------------------------------
__global__ void __launch_bounds__(256) score_kernel(
    const float* __restrict__ src,  const float* __restrict__ srct,
    const float* __restrict__ srcp,
    const float* __restrict__ seq,  const float* __restrict__ seqe,
    const float* __restrict__ seqt, const float* __restrict__ seqp,
    const int*   __restrict__ mask, float* __restrict__ out_attn)
{
    __shared__ float4 s_wkf[DM];
    __shared__ float s_score[NH][NN];
    __shared__ float s_qp[4][NH];
    __shared__ float s_qs[NH];

    int b = blockIdx.x;
    int t = threadIdx.x;

    const float4* gwkf = (const float4*)g_Wkf;
    s_wkf[t]       = gwkf[t];
    s_wkf[t + 256] = gwkf[t + 256];

    if (t < DK) {
        float a  = src[b * DK + t];
        float tt = srct[b * DK + t];
        float pp = srcp[b * DK + t];
        const float4* gwqf = (const float4*)g_Wqf;
        float4 w0 = gwqf[t];
        float4 w1 = gwqf[2 * DK + t];
        float4 w2 = gwqf[3 * DK + t];
        float q0 = a * w0.x + tt * w1.x + pp * w2.x;
        float q1 = a * w0.y + tt * w1.y + pp * w2.y;
        float q2 = a * w0.z + tt * w1.z + pp * w2.z;
        float q3 = a * w0.w + tt * w1.w + pp * w2.w;
#pragma unroll
        for (int o = 16; o > 0; o >>= 1) {
            q0 += __shfl_xor_sync(0xffffffffu, q0, o);
            q1 += __shfl_xor_sync(0xffffffffu, q1, o);
            q2 += __shfl_xor_sync(0xffffffffu, q2, o);
            q3 += __shfl_xor_sync(0xffffffffu, q3, o);
        }
        if ((t & 31) == 0) {
            int w = t >> 5;
            s_qp[w][0] = q0; s_qp[w][1] = q1; s_qp[w][2] = q2; s_qp[w][3] = q3;
        }
    }
    __syncthreads();

    {
        int w = t >> 5, lane = t & 31;
#pragma unroll
        for (int r = 0; r < 8; r++) {
            int k = w * 8 + r;
            float a0 = 0.f, a1 = 0.f, a2 = 0.f, a3 = 0.f;
#pragma unroll
            for (int seg = 0; seg < 4; seg++) {
                const float* kin = (seg == 0) ? seq : (seg == 1) ? seqe
                                  : (seg == 2) ? seqt : seqp;
                const float* row = kin + (size_t)(b * NN + k) * DK;
#pragma unroll
                for (int j = 0; j < 4; j++) {
                    float v = row[j * 32 + lane];
                    float4 wv = s_wkf[seg * DK + j * 32 + lane];
                    a0 += v * wv.x; a1 += v * wv.y;
                    a2 += v * wv.z; a3 += v * wv.w;
                }
            }
#pragma unroll
            for (int o = 16; o > 0; o >>= 1) {
                a0 += __shfl_xor_sync(0xffffffffu, a0, o);
                a1 += __shfl_xor_sync(0xffffffffu, a1, o);
                a2 += __shfl_xor_sync(0xffffffffu, a2, o);
                a3 += __shfl_xor_sync(0xffffffffu, a3, o);
            }
            if (lane == 0) {
                s_score[0][k] = a0; s_score[1][k] = a1;
                s_score[2][k] = a2; s_score[3][k] = a3;
            }
        }
    }
    __syncthreads();

    if (t < NH) s_qs[t] = s_qp[0][t] + s_qp[1][t] + s_qp[2][t] + s_qp[3][t];
    __syncthreads();

    if (t < 128) {
        int h = t >> 5, l = t & 31;
        float qs = s_qs[h];
        int m0 = mask[b * NN + l];
        int m1 = mask[b * NN + l + 32];
        float v0 = m0 ? -1e10f : qs + s_score[h][l];
        float v1 = m1 ? -1e10f : qs + s_score[h][l + 32];
        float mx = fmaxf(v0, v1);
#pragma unroll
        for (int o = 16; o > 0; o >>= 1) mx = fmaxf(mx, __shfl_xor_sync(0xffffffffu, mx, o));
        float e0 = expf(v0 - mx), e1 = expf(v1 - mx);
        float s = e0 + e1;
#pragma unroll
        for (int o = 16; o > 0; o >>= 1) s += __shfl_xor_sync(0xffffffffu, s, o);
        float inv = 1.f / s;
        e0 *= inv; e1 *= inv;
        out_attn[b * (NH * NN) + h * NN + l]      = e0;
        out_attn[b * (NH * NN) + h * NN + l + 32] = e1;
        g_attnT[(size_t)(b * NN + l) * NH + h]      = e0;
        g_attnT[(size_t)(b * NN + l + 32) * NH + h] = e1;
    }
}

// ---------------------------------------------------------------------------
// K2: fused ctx-stream + GEMM chain. TB=16 batches/CTA, 128 CTAs, block 512,
// 184KB smem, 1 CTA/SM (single wave). FFMA2 everywhere. Halved weight L2
// traffic vs TB=8.
// ---------------------------------------------------------------------------
#define SM_CTX  0        // [16][2048] f (32768) ; aliases: ln [16][512], h1
#define SM_ATT  32768    // [16][64] float4 (4096 f)
#define SM_OUT  36864    // [16][512]  (8192 f)  ; alias: part [3][16][128]
#define SM_SRC  45056    // [16][128]  (2048 f)
#define SM_TOTF 47104
#define SM_H1   8192     // alias in ctx region (after ln's 8192 floats)

__global__ void __launch_bounds__(512, 1) tail_kernel(
    const float* __restrict__ src,  const float* __restrict__ srct,
    const float* __restrict__ srcp,
    const float* __restrict__ seq,  const float* __restrict__ seqe,
    const float* __restrict__ seqt, const float* __restrict__ seqp,
    const float* __restrict__ Wv,   const float* __restrict__ fcw,
    const float* __restrict__ fcb,  const float* __restrict__ lng,
    const float* __restrict__ lnb,  const float* __restrict__ fc1w,
    const float* __restrict__ fc1b, const float* __restrict__ fc2w,
    const float* __restrict__ fc2b, float* __restrict__ zout)
{
    extern __shared__ float sm[];
    ulonglong2* ctxU = (ulonglong2*)sm;
    float4*     att4 = (float4*)(sm + SM_ATT);
    float*      out_s = sm + SM_OUT;
    ulonglong2* outU  = (ulonglong2*)out_s;
    float*      src_s = sm + SM_SRC;
    ulonglong2* srcU  = (ulonglong2*)src_s;
    float*      ln_s  = sm;
    ulonglong2* lnU   = (ulonglong2*)sm;
    float*      h1_s  = sm + SM_H1;
    ulonglong2* h1U   = (ulonglong2*)h1_s;
    float*      part  = out_s;            // alias, phases 5/6 only

    int t = threadIdx.x;
    int b0 = blockIdx.x * TB;

    // stage attn (transposed) + src
    {
        const float4* ga = (const float4*)(g_attnT + (size_t)b0 * NN * NH);
        for (int idx = t; idx < TB * NN; idx += 512) att4[idx] = ga[idx];
        const float4* gs = (const float4*)(src + (size_t)b0 * DK);
        float4* s4 = (float4*)src_s;
        for (int idx = t; idx < TB * DK / 4; idx += 512) s4[idx] = gs[idx];
    }
    __syncthreads();

    int rg = t >> 7;          // 0..3
    int c4 = t & 127;

    // Phase 1: ctx[r][h][i] = sum_k attn[r][k][h] * k_in[r][k][i]
    // 2 independent row streams per thread + 1-deep prefetch.
    {
        int seg = c4 >> 5, col = c4 & 31;
        const float* kin = (seg == 0) ? seq : (seg == 1) ? seqe
                          : (seg == 2) ? seqt : seqp;
#pragma unroll 1
        for (int rp = 0; rp < 2; rp++) {
            int r0 = rg * 4 + rp * 2;
            int r1 = r0 + 1;
            const ulonglong2* p0 = (const ulonglong2*)(kin + (size_t)(b0 + r0) * NN * DK) + col;
            const ulonglong2* p1 = (const ulonglong2*)(kin + (size_t)(b0 + r1) * NN * DK) + col;
            ull Ax[NH], Ay[NH], Bx[NH], By[NH];
#pragma unroll
            for (int h = 0; h < NH; h++) { Ax[h] = 0; Ay[h] = 0; Bx[h] = 0; By[h] = 0; }
            ulonglong2 va = p0[0], vb = p1[0];
#pragma unroll 4
            for (int k = 0; k < NN; k++) {
                ulonglong2 van, vbn;
                if (k < NN - 1) { van = p0[(k + 1) * 32]; vbn = p1[(k + 1) * 32]; }
                float4 a0 = att4[r0 * NN + k];
                float4 a1 = att4[r1 * NN + k];
                ull e00 = pk(a0.x, a0.x), e01 = pk(a0.y, a0.y);
                ull e02 = pk(a0.z, a0.z), e03 = pk(a0.w, a0.w);
                ull e10 = pk(a1.x, a1.x), e11 = pk(a1.y, a1.y);
                ull e12 = pk(a1.z, a1.z), e13 = pk(a1.w, a1.w);
                fma2(Ax[0], e00, va.x); fma2(Ay[0], e00, va.y);
                fma2(Ax[1], e01, va.x); fma2(Ay[1], e01, va.y);
                fma2(Ax[2], e02, va.x); fma2(Ay[2], e02, va.y);
                fma2(Ax[3], e03, va.x); fma2(Ay[3], e03, va.y);
                fma2(Bx[0], e10, vb.x); fma2(By[0], e10, vb.y);
                fma2(Bx[1], e11, vb.x); fma2(By[1], e11, vb.y);
                fma2(Bx[2], e12, vb.x); fma2(By[2], e12, vb.y);
                fma2(Bx[3], e13, vb.x); fma2(By[3], e13, vb.y);
                va = van; vb = vbn;
            }
#pragma unroll
            for (int h = 0; h < NH; h++) {
                ulonglong2 u; u.x = Ax[h]; u.y = Ay[h];
                ctxU[r0 * 512 + h * 128 + c4] = u;
                ulonglong2 w; w.x = Bx[h]; w.y = By[h];
                ctxU[r1 * 512 + h * 128 + c4] = w;
            }
        }
    }
    __syncthreads();

    int h = rg, d = c4;

    // Phase 2: out[r][h*128+d] = sum_i ctx[r][h][i] * Wv[i][h*128+d]
    {
        ull acc[TB];
#pragma unroll
        for (int r = 0; r < TB; r++) acc[r] = 0;
        const float* wcol = Wv + h * DK + d;
#pragma unroll 2
        for (int i4 = 0; i4 < 128; i4++) {
            int i = i4 * 4;
            float w0 = wcol[(i + 0) * DM], w1 = wcol[(i + 1) * DM];
            float w2 = wcol[(i + 2) * DM], w3 = wcol[(i + 3) * DM];
            ull wA = pk(w0, w1), wB = pk(w2, w3);
#pragma unroll
            for (int r = 0; r < TB; r++) {
                ulonglong2 c = ctxU[r * 512 + h * 128 + i4];   // broadcast
                fma2(acc[r], c.x, wA);
                fma2(acc[r], c.y, wB);
            }
        }
#pragma unroll
        for (int r = 0; r < TB; r++) {
            float2 f = up(acc[r]);
            out_s[r * DM + h * DK + d] = f.x + f.y;
        }
    }
    __syncthreads();

    // Phase 3: fc + leaky -> ln_s ; thread owns col t (512 cols)
    {
        ull acc[TB];
#pragma unroll
        for (int r = 0; r < TB; r++) acc[r] = 0;
        const float* wcol = fcw + t;
#pragma unroll 2
        for (int i4 = 0; i4 < 128; i4++) {
            int i = i4 * 4;
            float w0 = wcol[(i + 0) * DM], w1 = wcol[(i + 1) * DM];
            float w2 = wcol[(i + 2) * DM], w3 = wcol[(i + 3) * DM];
            ull wA = pk(w0, w1), wB = pk(w2, w3);
#pragma unroll
            for (int r = 0; r < TB; r++) {
                ulonglong2 x = outU[r * 128 + i4];             // broadcast
                fma2(acc[r], x.x, wA);
                fma2(acc[r], x.y, wB);
            }
        }
        float bb = fcb[t];
#pragma unroll
        for (int r = 0; r < TB; r++) {
            float2 f = up(acc[r]);
            float v = f.x + f.y + bb;
            v = (v > 0.f) ? v : 0.2f * v;
            ln_s[r * DM + t] = v;
        }
    }
    __syncthreads();

    // Phase 4: residual (+q_in) + layernorm, warp w -> row w (16 warps)
    {
        int w = t >> 5, l = t & 31;
        int gb = b0 + w;
        float y[16];
        float sum = 0.f, sumsq = 0.f;
#pragma unroll
        for (int e = 0; e < 16; e++) {
            int j = l + e * 32;
            float q;
            if (j < 128)       q = src_s[w * DK + j];
            else if (j < 256)  q = 0.f;
            else if (j < 384)  q = srct[(size_t)gb * DK + (j - 256)];
            else               q = srcp[(size_t)gb * DK + (j - 384)];
            float v = ln_s[w * DM + j] + q;
            y[e] = v; sum += v; sumsq += v * v;
        }
#pragma unroll
        for (int o = 16; o > 0; o >>= 1) {
            sum   += __shfl_xor_sync(0xffffffffu, sum, o);
            sumsq += __shfl_xor_sync(0xffffffffu, sumsq, o);
        }
        float mu  = sum * (1.f / 512.f);
        float var = sumsq * (1.f / 512.f) - mu * mu;
        float inv = rsqrtf(var + 1e-5f);
#pragma unroll
        for (int e = 0; e < 16; e++) {
            int j = l + e * 32;
            ln_s[w * DM + j] = (y[e] - mu) * inv * lng[j] + lnb[j];
        }
    }
    __syncthreads();

    int q = rg;   // K-quarter 0..3

    // Phase 5: fc1 (K=640, split 4 ways) + relu -> h1_s
    {
        ull acc[TB];
#pragma unroll
        for (int r = 0; r < TB; r++) acc[r] = 0;
        const float* wcol = fc1w + d;
        int i40 = q * 32;
#pragma unroll 2
        for (int i4 = i40; i4 < i40 + 32; i4++) {
            int j = i4 * 4;
            float w0 = wcol[(j + 0) * DK], w1 = wcol[(j + 1) * DK];
            float w2 = wcol[(j + 2) * DK], w3 = wcol[(j + 3) * DK];
            ull wA = pk(w0, w1), wB = pk(w2, w3);
#pragma unroll
            for (int r = 0; r < TB; r++) {
                ulonglong2 x = lnU[r * 128 + i4];              // broadcast
                fma2(acc[r], x.x, wA); fma2(acc[r], x.y, wB);
            }
        }
        int j40 = q * 8;
#pragma unroll 2
        for (int j4 = j40; j4 < j40 + 8; j4++) {
            int j = j4 * 4;
            float w0 = wcol[(DM + j + 0) * DK], w1 = wcol[(DM + j + 1) * DK];
            float w2 = wcol[(DM + j + 2) * DK], w3 = wcol[(DM + j + 3) * DK];
            ull wA = pk(w0, w1), wB = pk(w2, w3);
#pragma unroll
            for (int r = 0; r < TB; r++) {
                ulonglong2 x = srcU[r * 32 + j4];              // broadcast
                fma2(acc[r], x.x, wA); fma2(acc[r], x.y, wB);
            }
        }
        if (q > 0) {
#pragma unroll
            for (int r = 0; r < TB; r++) {
                float2 f = up(acc[r]);
                part[(q - 1) * 2048 + r * 128 + d] = f.x + f.y;
            }
        }
        __syncthreads();
        if (q == 0) {
            float bb = fc1b[d];
#pragma unroll
            for (int r = 0; r < TB; r++) {
                float2 f = up(acc[r]);
                float v = f.x + f.y + part[0 * 2048 + r * 128 + d]
                        + part[1 * 2048 + r * 128 + d]
                        + part[2 * 2048 + r * 128 + d] + bb;
                h1_s[r * DK + d] = fmaxf(v, 0.f);
            }
        }
        __syncthreads();
    }

    // Phase 6: fc2 (K=128, split 4 ways) -> z
    {
        ull acc[TB];
#pragma unroll
        for (int r = 0; r < TB; r++) acc[r] = 0;
        const float* wcol = fc2w + d;
        int j40 = q * 8;
#pragma unroll 2
        for (int j4 = j40; j4 < j40 + 8; j4++) {
            int j = j4 * 4;
            float w0 = wcol[(j + 0) * DK], w1 = wcol[(j + 1) * DK];
            float w2 = wcol[(j + 2) * DK], w3 = wcol[(j + 3) * DK];
            ull wA = pk(w0, w1), wB = pk(w2, w3);
#pragma unroll
            for (int r = 0; r < TB; r++) {
                ulonglong2 x = h1U[r * 32 + j4];               // broadcast
                fma2(acc[r], x.x, wA); fma2(acc[r], x.y, wB);
            }
        }
        if (q > 0) {
#pragma unroll
            for (int r = 0; r < TB; r++) {
                float2 f = up(acc[r]);
                part[(q - 1) * 2048 + r * 128 + d] = f.x + f.y;
            }
        }
        __syncthreads();
        if (q == 0) {
            float bb = fc2b[d];
#pragma unroll
            for (int r = 0; r < TB; r++) {
                float2 f = up(acc[r]);
                zout[(size_t)(b0 + r) * DK + d] = f.x + f.y
                    + part[0 * 2048 + r * 128 + d]
                    + part[1 * 2048 + r * 128 + d]
                    + part[2 * 2048 + r * 128 + d] + bb;
            }
        }
    }
}

// ---------------------------------------------------------------------------
extern "C" void kernel_launch(void* const* d_in, const int* in_sizes, int n_in,
                              void* d_out, int out_size) {
    (void)in_sizes; (void)n_in; (void)out_size;
    const float* src   = (const float*)d_in[0];
    const float* src_t = (const float*)d_in[1];
    const float* src_p = (const float*)d_in[2];
    const float* seq   = (const float*)d_in[3];
    const float* seq_t = (const float*)d_in[4];
    const float* seq_e = (const float*)d_in[5];
    const float* seq_p = (const float*)d_in[6];
    const int*   mask  = (const int*)d_in[7];
    const float* Wq    = (const float*)d_in[8];
    const float* Wk    = (const float*)d_in[9];
    const float* Wv    = (const float*)d_in[10];
    const float* w_map = (const float*)d_in[11];
    const float* fc_w  = (const float*)d_in[12];
    const float* fc_b  = (const float*)d_in[13];
    const float* ln_g  = (const float*)d_in[14];
    const float* ln_b  = (const float*)d_in[15];
    const float* fc1_w = (const float*)d_in[16];
    const float* fc1_b = (const float*)d_in[17];
    const float* fc2_w = (const float*)d_in[18];
    const float* fc2_b = (const float*)d_in[19];

    float* out      = (float*)d_out;
    float* z_out    = out;                 // [2048,1,128]
    float* attn_out = out + NB * DK;       // [2048,4,1,64]

    fold_kernel<<<DM, 128>>>(Wq, Wk, w_map);
    score_kernel<<<NB, 256>>>(src, src_t, src_p, seq, seq_e, seq_t, seq_p,
                              mask, attn_out);

    const int smem2 = SM_TOTF * (int)sizeof(float);
    cudaFuncSetAttribute(tail_kernel, cudaFuncAttributeMaxDynamicSharedMemorySize, smem2);
    tail_kernel<<<NB / TB, 512, smem2>>>(src, src_t, src_p,
                                         seq, seq_e, seq_t, seq_p,
                                         Wv, fc_w, fc_b, ln_g, ln_b,
                                         fc1_w, fc1_b, fc2_w, fc2_b, z_out);
}